// round 5
// baseline (speedup 1.0000x reference)
#include <cuda_runtime.h>
#include <cstdint>
#include <cstddef>

#define TM      128     // rows per CTA
#define NT      512     // threads (16 warps)
#define KC      32      // k-chunk
#define LATENT  256
#define NNODES  256
#define NROWS   65536
#define ZRS     36      // z row stride (floats): 16B-aligned rows, natural layout
#define ES      258     // e [k][node] stride (floats): even -> LDS.64 node pairs
#define STAGE_FLOATS (TM*ZRS + KC*ES)   // 4608 + 8256 = 12864
#define REDS    33
#define EPSF    1.1920929e-7f

typedef unsigned long long u64;

__device__ __forceinline__ u64 ffma2(u64 a, u64 b, u64 c) {
    u64 d;
    asm("fma.rn.f32x2 %0, %1, %2, %3;" : "=l"(d) : "l"(a), "l"(b), "l"(c));
    return d;
}
__device__ __forceinline__ u64 pack2(float x) {
    u64 d;
    asm("mov.b64 %0, {%1, %1};" : "=l"(d) : "f"(x));
    return d;
}
__device__ __forceinline__ u64 packf2(float lo, float hi) {
    u64 d;
    asm("mov.b64 %0, {%1, %2};" : "=l"(d) : "f"(lo), "f"(hi));
    return d;
}
__device__ __forceinline__ unsigned smem_u32(const void* p) {
    return (unsigned)__cvta_generic_to_shared(p);
}
__device__ __forceinline__ void cp16(unsigned dst, const void* src) {
    asm volatile("cp.async.cg.shared.global [%0], [%1], 16;" :: "r"(dst), "l"(src));
}
__device__ __forceinline__ void cp_commit() { asm volatile("cp.async.commit_group;"); }
__device__ __forceinline__ void cp_wait0()  { asm volatile("cp.async.wait_group 0;"); }

extern __shared__ float smf[];

// smem: stage0 [0,12864) stage1 [12864,25728); tail: e2(256) z2(128) bmu(128) rqs(128)
// reduction overlay (128*33*3 = 12672) fits in stage0 after GEMM.
#define SMEM_FLOATS (2*STAGE_FLOATS + 256 + 128 + 128 + 128)
#define SMEM_BYTES  (SMEM_FLOATS * 4)

__global__ void __launch_bounds__(NT, 1)
som_kernel(const float* __restrict__ Z, const float* __restrict__ E,
           const int* __restrict__ Alpha, float* __restrict__ out)
{
    float* e2   = smf + 2 * STAGE_FLOATS;
    float* z2   = e2 + NNODES;
    int*   bmuS = (int*)(z2 + TM);
    float* rqs  = (float*)(bmuS + TM);
    float* redv = smf;                     // overlays stage0 post-GEMM
    int*   redi = (int*)(smf + TM * REDS);
    float* reds = smf + 2 * TM * REDS;

    const int t  = threadIdx.x;
    const int R0 = blockIdx.x * TM;
    const int cg = t & 31;      // node pairs {2cg+64m}, m=0..3
    const int rg = t >> 5;      // 16 row groups of 8
    const int r0 = rg * 8;

    // ---- e2[j] = ||e_j||^2 ----
    if (t < NNODES) {
        const float4* er4 = (const float4*)(E + (size_t)t * LATENT);
        float s = 0.f;
        #pragma unroll 8
        for (int i = 0; i < 64; i++) { float4 v = er4[i]; s += v.x*v.x + v.y*v.y + v.z*v.z + v.w*v.w; }
        e2[t] = s;
    }

    // Z cp.async mapping: 2 granules/thread (1024 granules: row = g>>3, kq = g&7)
    const int g0row = t >> 3,            g0kq = t & 7;
    const int g1row = (t + NT) >> 3,     g1kq = (t + NT) & 7;
    // E LDG mapping: enode = t&255, ekq0 = t>>8; slices {ekq0+2i}, i=0..3
    const int enode = t & 255;
    const int ekq0  = t >> 8;

    u64 acc[8][4];
    #pragma unroll
    for (int r = 0; r < 8; r++)
        #pragma unroll
        for (int m = 0; m < 4; m++) acc[r][m] = 0ull;

    // ---- prologue: chunk 0 in flight ----
    {
        float* zs0 = smf;   // stage 0 z
        cp16(smem_u32(zs0 + g0row * ZRS + g0kq * 4), Z + (size_t)(R0 + g0row) * LATENT + g0kq * 4);
        cp16(smem_u32(zs0 + g1row * ZRS + g1kq * 4), Z + (size_t)(R0 + g1row) * LATENT + g1kq * 4);
        cp_commit();
    }
    float4 er[4];
    #pragma unroll
    for (int i = 0; i < 4; i++)
        er[i] = *(const float4*)(E + (size_t)enode * LATENT + (ekq0 + 2 * i) * 4);

    for (int c = 0; c < LATENT / KC; c++) {
        const int s = c & 1;
        float* zs = smf + s * STAGE_FLOATS;
        float* es = zs + TM * ZRS;

        // 1) store E prefetch regs -> this stage (transposed [k][node])
        #pragma unroll
        for (int i = 0; i < 4; i++) {
            float* q = es + (size_t)(4 * (ekq0 + 2 * i)) * ES + enode;
            q[0] = er[i].x; q[ES] = er[i].y; q[2*ES] = er[i].z; q[3*ES] = er[i].w;
        }
        // 2) z copies for this stage done + all threads past previous compute
        cp_wait0();
        __syncthreads();

        // 3) issue next chunk's loads (overlap with compute below)
        if (c < LATENT / KC - 1) {
            const int cb = (c + 1) * KC;
            float* zn = smf + (1 - s) * STAGE_FLOATS;
            cp16(smem_u32(zn + g0row * ZRS + g0kq * 4), Z + (size_t)(R0 + g0row) * LATENT + cb + g0kq * 4);
            cp16(smem_u32(zn + g1row * ZRS + g1kq * 4), Z + (size_t)(R0 + g1row) * LATENT + cb + g1kq * 4);
            cp_commit();
            #pragma unroll
            for (int i = 0; i < 4; i++)
                er[i] = *(const float4*)(E + (size_t)enode * LATENT + cb + (ekq0 + 2 * i) * 4);
        } else {
            cp_commit();   // keep wait_group balanced next iteration (none)
        }

        // 4) compute: 8 rows x 4 node-pairs, z broadcast window per 2k
        #pragma unroll 4
        for (int kk = 0; kk < KC; kk += 2) {
            float2 zw[8];
            #pragma unroll
            for (int r = 0; r < 8; r++)
                zw[r] = *(const float2*)(zs + (r0 + r) * ZRS + kk);
            #pragma unroll
            for (int h = 0; h < 2; h++) {
                const float* ek = es + (size_t)(kk + h) * ES + 2 * cg;
                u64 e0 = *(const u64*)(ek);
                u64 e1 = *(const u64*)(ek + 64);
                u64 e2v = *(const u64*)(ek + 128);
                u64 e3 = *(const u64*)(ek + 192);
                #pragma unroll
                for (int r = 0; r < 8; r++) {
                    u64 zp = pack2(h ? zw[r].y : zw[r].x);
                    acc[r][0] = ffma2(zp, e0,  acc[r][0]);
                    acc[r][1] = ffma2(zp, e1,  acc[r][1]);
                    acc[r][2] = ffma2(zp, e2v, acc[r][2]);
                    acc[r][3] = ffma2(zp, e3,  acc[r][3]);
                }
            }
        }
    }

    // ---- z2 from gmem re-read: thread t -> row t>>2, quarter t&3, shfl reduce ----
    {
        const int row = t >> 2, q = t & 3;
        const float4* zr4 = (const float4*)(Z + (size_t)(R0 + row) * LATENT + q * 64);
        float sacc = 0.f;
        #pragma unroll 4
        for (int i = 0; i < 16; i++) { float4 v = zr4[i]; sacc += v.x*v.x + v.y*v.y + v.z*v.z + v.w*v.w; }
        sacc += __shfl_xor_sync(0xffffffffu, sacc, 1);
        sacc += __shfl_xor_sync(0xffffffffu, sacc, 2);
        if (q == 0) z2[row] = sacc;
    }
    __syncthreads();   // z2 ready; GEMM stages dead -> reduction overlay safe

    // ---- alpha ----
    int ai = Alpha[0];
    float a = (ai > 0 && ai < 1000000) ? (float)ai : __int_as_float(ai);
    float inva = 1.0f / a;
    float coef = -(a + 1.0f) * 0.5f;

    // ---- epilogue: d, q, per-row local argmin + qsum ----
    float rmin[8], rsum[8];
    int   rid[8];
    #pragma unroll
    for (int r = 0; r < 8; r++) { rmin[r] = 3.4e38f; rsum[r] = 0.f; rid[r] = 0; }

    float z2v[8];
    #pragma unroll
    for (int r = 0; r < 8; r++) z2v[r] = z2[r0 + r];

    #pragma unroll
    for (int m = 0; m < 4; m++) {
        int j0 = 2 * cg + 64 * m, j1 = j0 + 1;
        float e20 = e2[j0], e21 = e2[j1];
        #pragma unroll
        for (int r = 0; r < 8; r++) {
            u64 av = acc[r][m];
            float dotl = __uint_as_float((unsigned)av);
            float doth = __uint_as_float((unsigned)(av >> 32));
            float dl = fmaxf(z2v[r] + e20 - 2.f * dotl, 0.f);
            float dh = fmaxf(z2v[r] + e21 - 2.f * doth, 0.f);
            float ql = exp2f(coef * __log2f(fmaf(dl, inva, 1.0f)));
            float qh = exp2f(coef * __log2f(fmaf(dh, inva, 1.0f)));
            if (dl < rmin[r]) { rmin[r] = dl; rid[r] = j0; }
            if (dh < rmin[r]) { rmin[r] = dh; rid[r] = j1; }
            rsum[r] += ql + qh;
            acc[r][m] = packf2(ql, qh);   // stash raw q
        }
    }
    #pragma unroll
    for (int r = 0; r < 8; r++) {
        int row = r0 + r;
        redv[row * REDS + cg] = rmin[r];
        redi[row * REDS + cg] = rid[r];
        reds[row * REDS + cg] = rsum[r];
    }
    __syncthreads();

    // ---- cross-lane reduction: bmu (lowest-index tie-break) + 1/qsum ----
    if (t < TM) {
        float bv = 3.4e38f; int bi = 0x7fffffff; float s = 0.f;
        #pragma unroll 4
        for (int g = 0; g < 32; g++) {
            float v = redv[t * REDS + g];
            int   i = redi[t * REDS + g];
            s += reds[t * REDS + g];
            if (v < bv || (v == bv && i < bi)) { bv = v; bi = i; }
        }
        bmuS[t] = bi;
        rqs[t]  = 1.0f / s;
    }
    __syncthreads();

    // ---- outputs: [z_q | z_q_neighbors | q | bmu] ----
    const size_t NBOFF  = (size_t)NROWS * 256;
    const size_t QOFF   = (size_t)NROWS * 1536;
    const size_t BMUOFF = (size_t)NROWS * 1792;

    // q: STG.64, lanes cover contiguous node pairs
    #pragma unroll
    for (int r = 0; r < 8; r++) {
        int row = r0 + r;
        float rq = rqs[row];
        u64* dst = (u64*)(out + QOFF + (size_t)(R0 + row) * NNODES + 2 * cg);
        #pragma unroll
        for (int m = 0; m < 4; m++) {
            u64 av = acc[r][m];
            float ql = fmaf(__uint_as_float((unsigned)av),         rq, EPSF);
            float qh = fmaf(__uint_as_float((unsigned)(av >> 32)), rq, EPSF);
            dst[32 * m] = packf2(ql, qh);
        }
    }

    if (t < TM) out[BMUOFF + R0 + t] = (float)bmuS[t];

    // z_q + neighbor gathers: 6 copies/row, one warp per copy
    const int lane = t & 31, wid = t >> 5;
    for (int cp = wid; cp < TM * 6; cp += 16) {
        int row = cp / 6;
        int s   = cp - row * 6;
        int b   = bmuS[row];
        int idx;
        if (s <= 1) {
            idx = b;
        } else {
            int k1 = b >> 4, k2 = b & 15;
            if      (s == 2) idx = (((k1 + 15) & 15) << 4) + k2;   // up
            else if (s == 3) idx = (((k1 + 1)  & 15) << 4) + k2;   // down
            else if (s == 4) idx = (k1 << 4) + ((k2 + 1)  & 15);   // right
            else             idx = (k1 << 4) + ((k2 + 15) & 15);   // left
        }
        const float4* src = (const float4*)(E + (size_t)idx * LATENT);
        float4 a0 = src[lane], a1 = src[lane + 32];
        float* dstp = (s == 0)
            ? out + (size_t)(R0 + row) * LATENT
            : out + NBOFF + ((size_t)(R0 + row) * 5 + (s - 1)) * LATENT;
        float4* d4 = (float4*)dstp;
        d4[lane]      = a0;
        d4[lane + 32] = a1;
    }
}

extern "C" void kernel_launch(void* const* d_in, const int* in_sizes, int n_in,
                              void* d_out, int out_size) {
    const float* Z = (const float*)d_in[0];
    const float* E = (const float*)d_in[1];
    const int*   A = (const int*)d_in[2];
    float* out = (float*)d_out;

    cudaFuncSetAttribute(som_kernel, cudaFuncAttributeMaxDynamicSharedMemorySize, SMEM_BYTES);
    som_kernel<<<NROWS / TM, NT, SMEM_BYTES>>>(Z, E, A, out);
}

// round 6
// speedup vs baseline: 1.3586x; 1.3586x over previous
#include <cuda_runtime.h>
#include <cstdint>
#include <cstddef>

#define TM      128     // rows per CTA
#define NT      512     // threads (16 warps)
#define KC      32      // k-chunk
#define LATENT  256
#define NNODES  256
#define NROWS   65536
#define ZRS     36      // z row stride (floats): 16B-aligned rows, natural layout
#define ES      258     // e [k][node] stride (floats): even -> LDS.64 node pairs
#define STAGE_FLOATS (TM*ZRS + KC*ES)   // 4608 + 8256 = 12864
#define REDS    33
#define EPSF    1.1920929e-7f

typedef unsigned long long u64;

__device__ __forceinline__ u64 ffma2(u64 a, u64 b, u64 c) {
    u64 d;
    asm("fma.rn.f32x2 %0, %1, %2, %3;" : "=l"(d) : "l"(a), "l"(b), "l"(c));
    return d;
}
__device__ __forceinline__ u64 pack2(float x) {
    u64 d;
    asm("mov.b64 %0, {%1, %1};" : "=l"(d) : "f"(x));
    return d;
}
__device__ __forceinline__ u64 packf2(float lo, float hi) {
    u64 d;
    asm("mov.b64 %0, {%1, %2};" : "=l"(d) : "f"(lo), "f"(hi));
    return d;
}
__device__ __forceinline__ unsigned smem_u32(const void* p) {
    return (unsigned)__cvta_generic_to_shared(p);
}
__device__ __forceinline__ void cp16(unsigned dst, const void* src) {
    asm volatile("cp.async.cg.shared.global [%0], [%1], 16;" :: "r"(dst), "l"(src));
}
__device__ __forceinline__ void cp_commit() { asm volatile("cp.async.commit_group;"); }
__device__ __forceinline__ void cp_wait0()  { asm volatile("cp.async.wait_group 0;"); }

extern __shared__ float smf[];

// smem: stage0 [0,12864) stage1 [12864,25728); tail: e2(256) z2(128) bmu(128) rqs(128)
// reduction overlay (128*33*3 = 12672) fits in stage0 after GEMM.
#define SMEM_FLOATS (2*STAGE_FLOATS + 256 + 128 + 128 + 128)
#define SMEM_BYTES  (SMEM_FLOATS * 4)

__global__ void __launch_bounds__(NT, 1)
som_kernel(const float* __restrict__ Z, const float* __restrict__ E,
           const int* __restrict__ Alpha, float* __restrict__ out)
{
    float* e2   = smf + 2 * STAGE_FLOATS;
    float* z2   = e2 + NNODES;
    int*   bmuS = (int*)(z2 + TM);
    float* rqs  = (float*)(bmuS + TM);
    float* redv = smf;                     // overlays stage0 post-GEMM
    int*   redi = (int*)(smf + TM * REDS);
    float* reds = smf + 2 * TM * REDS;

    const int t  = threadIdx.x;
    const int R0 = blockIdx.x * TM;
    const int cg = t & 31;      // node pairs {2cg+64m}, m=0..3
    const int rg = t >> 5;      // 16 row groups of 8
    const int r0 = rg * 8;

    // ---- e2[j] = ||e_j||^2 ----
    if (t < NNODES) {
        const float4* er4 = (const float4*)(E + (size_t)t * LATENT);
        float s = 0.f;
        #pragma unroll 8
        for (int i = 0; i < 64; i++) { float4 v = er4[i]; s += v.x*v.x + v.y*v.y + v.z*v.z + v.w*v.w; }
        e2[t] = s;
    }

    // Z cp.async mapping: 2 granules/thread (1024 granules: row = g>>3, kq = g&7)
    const int g0row = t >> 3,            g0kq = t & 7;
    const int g1row = (t + NT) >> 3,     g1kq = (t + NT) & 7;
    // E LDG mapping: enode = t&255, ekq0 = t>>8; slices {ekq0+2i}, i=0..3
    const int enode = t & 255;
    const int ekq0  = t >> 8;

    u64 acc[8][4];
    #pragma unroll
    for (int r = 0; r < 8; r++)
        #pragma unroll
        for (int m = 0; m < 4; m++) acc[r][m] = 0ull;

    // ---- prologue: chunk 0 in flight ----
    {
        float* zs0 = smf;   // stage 0 z
        cp16(smem_u32(zs0 + g0row * ZRS + g0kq * 4), Z + (size_t)(R0 + g0row) * LATENT + g0kq * 4);
        cp16(smem_u32(zs0 + g1row * ZRS + g1kq * 4), Z + (size_t)(R0 + g1row) * LATENT + g1kq * 4);
        cp_commit();
    }
    float4 er[4];
    #pragma unroll
    for (int i = 0; i < 4; i++)
        er[i] = *(const float4*)(E + (size_t)enode * LATENT + (ekq0 + 2 * i) * 4);

    for (int c = 0; c < LATENT / KC; c++) {
        const int s = c & 1;
        float* zs = smf + s * STAGE_FLOATS;
        float* es = zs + TM * ZRS;

        // 1) store E prefetch regs -> this stage (transposed [k][node])
        #pragma unroll
        for (int i = 0; i < 4; i++) {
            float* q = es + (size_t)(4 * (ekq0 + 2 * i)) * ES + enode;
            q[0] = er[i].x; q[ES] = er[i].y; q[2*ES] = er[i].z; q[3*ES] = er[i].w;
        }
        // 2) z copies for this stage done + all threads past previous compute
        cp_wait0();
        __syncthreads();

        // 3) issue next chunk's loads (overlap with compute below)
        if (c < LATENT / KC - 1) {
            const int cb = (c + 1) * KC;
            float* zn = smf + (1 - s) * STAGE_FLOATS;
            cp16(smem_u32(zn + g0row * ZRS + g0kq * 4), Z + (size_t)(R0 + g0row) * LATENT + cb + g0kq * 4);
            cp16(smem_u32(zn + g1row * ZRS + g1kq * 4), Z + (size_t)(R0 + g1row) * LATENT + cb + g1kq * 4);
            cp_commit();
            #pragma unroll
            for (int i = 0; i < 4; i++)
                er[i] = *(const float4*)(E + (size_t)enode * LATENT + cb + (ekq0 + 2 * i) * 4);
        } else {
            cp_commit();   // keep wait_group balanced next iteration (none)
        }

        // 4) compute: 8 rows x 4 node-pairs, z broadcast window per 2k
        #pragma unroll 4
        for (int kk = 0; kk < KC; kk += 2) {
            float2 zw[8];
            #pragma unroll
            for (int r = 0; r < 8; r++)
                zw[r] = *(const float2*)(zs + (r0 + r) * ZRS + kk);
            #pragma unroll
            for (int h = 0; h < 2; h++) {
                const float* ek = es + (size_t)(kk + h) * ES + 2 * cg;
                u64 e0 = *(const u64*)(ek);
                u64 e1 = *(const u64*)(ek + 64);
                u64 e2v = *(const u64*)(ek + 128);
                u64 e3 = *(const u64*)(ek + 192);
                #pragma unroll
                for (int r = 0; r < 8; r++) {
                    u64 zp = pack2(h ? zw[r].y : zw[r].x);
                    acc[r][0] = ffma2(zp, e0,  acc[r][0]);
                    acc[r][1] = ffma2(zp, e1,  acc[r][1]);
                    acc[r][2] = ffma2(zp, e2v, acc[r][2]);
                    acc[r][3] = ffma2(zp, e3,  acc[r][3]);
                }
            }
        }
    }

    // ---- z2 from gmem re-read: thread t -> row t>>2, quarter t&3, shfl reduce ----
    {
        const int row = t >> 2, q = t & 3;
        const float4* zr4 = (const float4*)(Z + (size_t)(R0 + row) * LATENT + q * 64);
        float sacc = 0.f;
        #pragma unroll 4
        for (int i = 0; i < 16; i++) { float4 v = zr4[i]; sacc += v.x*v.x + v.y*v.y + v.z*v.z + v.w*v.w; }
        sacc += __shfl_xor_sync(0xffffffffu, sacc, 1);
        sacc += __shfl_xor_sync(0xffffffffu, sacc, 2);
        if (q == 0) z2[row] = sacc;
    }
    __syncthreads();   // z2 ready; GEMM stages dead -> reduction overlay safe

    // ---- alpha ----
    int ai = Alpha[0];
    float a = (ai > 0 && ai < 1000000) ? (float)ai : __int_as_float(ai);
    float inva = 1.0f / a;
    float coef = -(a + 1.0f) * 0.5f;

    // ---- epilogue: d, q, per-row local argmin + qsum ----
    float rmin[8], rsum[8];
    int   rid[8];
    #pragma unroll
    for (int r = 0; r < 8; r++) { rmin[r] = 3.4e38f; rsum[r] = 0.f; rid[r] = 0; }

    float z2v[8];
    #pragma unroll
    for (int r = 0; r < 8; r++) z2v[r] = z2[r0 + r];

    #pragma unroll
    for (int m = 0; m < 4; m++) {
        int j0 = 2 * cg + 64 * m, j1 = j0 + 1;
        float e20 = e2[j0], e21 = e2[j1];
        #pragma unroll
        for (int r = 0; r < 8; r++) {
            u64 av = acc[r][m];
            float dotl = __uint_as_float((unsigned)av);
            float doth = __uint_as_float((unsigned)(av >> 32));
            float dl = fmaxf(z2v[r] + e20 - 2.f * dotl, 0.f);
            float dh = fmaxf(z2v[r] + e21 - 2.f * doth, 0.f);
            float ql = exp2f(coef * __log2f(fmaf(dl, inva, 1.0f)));
            float qh = exp2f(coef * __log2f(fmaf(dh, inva, 1.0f)));
            if (dl < rmin[r]) { rmin[r] = dl; rid[r] = j0; }
            if (dh < rmin[r]) { rmin[r] = dh; rid[r] = j1; }
            rsum[r] += ql + qh;
            acc[r][m] = packf2(ql, qh);   // stash raw q
        }
    }
    #pragma unroll
    for (int r = 0; r < 8; r++) {
        int row = r0 + r;
        redv[row * REDS + cg] = rmin[r];
        redi[row * REDS + cg] = rid[r];
        reds[row * REDS + cg] = rsum[r];
    }
    __syncthreads();

    // ---- cross-lane reduction: bmu (lowest-index tie-break) + 1/qsum ----
    if (t < TM) {
        float bv = 3.4e38f; int bi = 0x7fffffff; float s = 0.f;
        #pragma unroll 4
        for (int g = 0; g < 32; g++) {
            float v = redv[t * REDS + g];
            int   i = redi[t * REDS + g];
            s += reds[t * REDS + g];
            if (v < bv || (v == bv && i < bi)) { bv = v; bi = i; }
        }
        bmuS[t] = bi;
        rqs[t]  = 1.0f / s;
    }
    __syncthreads();

    // ---- outputs: [z_q | z_q_neighbors | q | bmu] ----
    const size_t NBOFF  = (size_t)NROWS * 256;
    const size_t QOFF   = (size_t)NROWS * 1536;
    const size_t BMUOFF = (size_t)NROWS * 1792;

    // q: STG.64, lanes cover contiguous node pairs
    #pragma unroll
    for (int r = 0; r < 8; r++) {
        int row = r0 + r;
        float rq = rqs[row];
        u64* dst = (u64*)(out + QOFF + (size_t)(R0 + row) * NNODES + 2 * cg);
        #pragma unroll
        for (int m = 0; m < 4; m++) {
            u64 av = acc[r][m];
            float ql = fmaf(__uint_as_float((unsigned)av),         rq, EPSF);
            float qh = fmaf(__uint_as_float((unsigned)(av >> 32)), rq, EPSF);
            dst[32 * m] = packf2(ql, qh);
        }
    }

    if (t < TM) out[BMUOFF + R0 + t] = (float)bmuS[t];

    // z_q + neighbor gathers: 6 copies/row, one warp per copy
    const int lane = t & 31, wid = t >> 5;
    for (int cp = wid; cp < TM * 6; cp += 16) {
        int row = cp / 6;
        int s   = cp - row * 6;
        int b   = bmuS[row];
        int idx;
        if (s <= 1) {
            idx = b;
        } else {
            int k1 = b >> 4, k2 = b & 15;
            if      (s == 2) idx = (((k1 + 15) & 15) << 4) + k2;   // up
            else if (s == 3) idx = (((k1 + 1)  & 15) << 4) + k2;   // down
            else if (s == 4) idx = (k1 << 4) + ((k2 + 1)  & 15);   // right
            else             idx = (k1 << 4) + ((k2 + 15) & 15);   // left
        }
        const float4* src = (const float4*)(E + (size_t)idx * LATENT);
        float4 a0 = src[lane], a1 = src[lane + 32];
        float* dstp = (s == 0)
            ? out + (size_t)(R0 + row) * LATENT
            : out + NBOFF + ((size_t)(R0 + row) * 5 + (s - 1)) * LATENT;
        float4* d4 = (float4*)dstp;
        d4[lane]      = a0;
        d4[lane + 32] = a1;
    }
}

extern "C" void kernel_launch(void* const* d_in, const int* in_sizes, int n_in,
                              void* d_out, int out_size) {
    const float* Z = (const float*)d_in[0];
    const float* E = (const float*)d_in[1];
    const int*   A = (const int*)d_in[2];
    float* out = (float*)d_out;

    cudaFuncSetAttribute(som_kernel, cudaFuncAttributeMaxDynamicSharedMemorySize, SMEM_BYTES);
    som_kernel<<<NROWS / TM, NT, SMEM_BYTES>>>(Z, E, A, out);
}

// round 8
// speedup vs baseline: 2.8131x; 2.0705x over previous
#include <cuda_runtime.h>
#include <cuda_bf16.h>
#include <cstdint>
#include <cstddef>

typedef unsigned long long u64;
typedef unsigned int u32;

#define NROWS  65536
#define LATENT 256
#define NNODES 256
#define TM     128
#define NT     512
#define EPSF   1.1920929e-7f
#define MARGIN 0.08f
#define CAP    8192

// ---- smem layout (byte offsets from 1KB-aligned base) ----
#define SA_OFF(s) ((s) * 49152)            // A stage: 128 rows x 128B bf16
#define SB_OFF(s) ((s) * 49152 + 16384)    // B stage: 256 rows x 128B bf16
#define T_E2RAW 98304
#define T_E2D   99328
#define T_Z2P   100352
#define T_Z2RAW 102400
#define T_Z2PP  102912
#define T_RQM   103424
#define T_RQS   105472
#define T_QTHR  107520
#define T_RQSI  108032
#define T_KEY   108544
#define T_BMU   109568
#define T_CNT   110080
#define SMEM_BYTES (110096 + 1024)

__device__ __align__(1024) unsigned char g_Bt[4][256 * 64 * 2];  // prebuilt bf16 E tiles
__device__ float g_e2[NNODES];

__device__ __forceinline__ u32 smaddr(const void* p) { return (u32)__cvta_generic_to_shared(p); }
__device__ __forceinline__ u32 toff(int row, int kbyte) {
    u32 o = (u32)(row * 128 + kbyte);
    return o ^ ((o >> 3) & 0x70);          // SW128
}
__device__ __forceinline__ void cp16(u32 dst, const void* src) {
    asm volatile("cp.async.cg.shared.global [%0], [%1], 16;" :: "r"(dst), "l"(src));
}
__device__ __forceinline__ void cp_commit() { asm volatile("cp.async.commit_group;" ::: "memory"); }
__device__ __forceinline__ void cp_wait0()  { asm volatile("cp.async.wait_group 0;" ::: "memory"); }
__device__ __forceinline__ void ldsm4(u32* r, u32 addr) {
    asm volatile("ldmatrix.sync.aligned.m8n8.x4.shared.b16 {%0,%1,%2,%3}, [%4];"
                 : "=r"(r[0]), "=r"(r[1]), "=r"(r[2]), "=r"(r[3]) : "r"(addr));
}
__device__ __forceinline__ void mma16816(float* d, const u32* a, u32 b0, u32 b1) {
    asm volatile("mma.sync.aligned.m16n8k16.row.col.f32.bf16.bf16.f32 "
                 "{%0,%1,%2,%3}, {%4,%5,%6,%7}, {%8,%9}, {%0,%1,%2,%3};"
                 : "+f"(d[0]), "+f"(d[1]), "+f"(d[2]), "+f"(d[3])
                 : "r"(a[0]), "r"(a[1]), "r"(a[2]), "r"(a[3]), "r"(b0), "r"(b1));
}
// f32x2 helpers
__device__ __forceinline__ u64 packf2(float lo, float hi) {
    u64 d; asm("mov.b64 %0, {%1, %2};" : "=l"(d) : "f"(lo), "f"(hi)); return d;
}
__device__ __forceinline__ void unpackf2(float& lo, float& hi, u64 v) {
    asm("mov.b64 {%0, %1}, %2;" : "=f"(lo), "=f"(hi) : "l"(v));
}
__device__ __forceinline__ u64 add2(u64 a, u64 b) {
    u64 d; asm("add.rn.f32x2 %0, %1, %2;" : "=l"(d) : "l"(a), "l"(b)); return d;
}
__device__ __forceinline__ u64 mul2(u64 a, u64 b) {
    u64 d; asm("mul.rn.f32x2 %0, %1, %2;" : "=l"(d) : "l"(a), "l"(b)); return d;
}
__device__ __forceinline__ u64 fma2(u64 a, u64 b, u64 c) {
    u64 d; asm("fma.rn.f32x2 %0, %1, %2, %3;" : "=l"(d) : "l"(a), "l"(b), "l"(c)); return d;
}

// ---------- prep: e2 + bf16 swizzled E tiles ----------
__global__ void prep_kernel(const float* __restrict__ E) {
    int tid = blockIdx.x * 256 + threadIdx.x;  // 2048 threads
    if (tid < NNODES) {
        const float4* er = (const float4*)(E + (size_t)tid * LATENT);
        float s = 0.f;
        #pragma unroll 8
        for (int i = 0; i < 64; i++) { float4 v = er[i]; s += v.x*v.x + v.y*v.y + v.z*v.z + v.w*v.w; }
        g_e2[tid] = s;
    }
    // 4 chunks x 256 nodes x 8 kgroups (8 elements each)
    for (int gi = tid; gi < 8192; gi += 2048) {
        int chunk = gi >> 11, node = (gi >> 3) & 255, kg = gi & 7;
        const float* src = E + (size_t)node * LATENT + chunk * 64 + kg * 8;
        __nv_bfloat16 h[8];
        #pragma unroll
        for (int i = 0; i < 8; i++) h[i] = __float2bfloat16(src[i]);
        *(uint4*)(g_Bt[chunk] + toff(node, kg * 16)) = *(uint4*)h;
    }
}

// ---------- main ----------
__global__ void __launch_bounds__(NT, 1)
som_main(const float* __restrict__ Z, const float* __restrict__ E,
         const int* __restrict__ Alpha, float* __restrict__ out)
{
    extern __shared__ char smraw[];
    char* SB = (char*)(((uintptr_t)smraw + 1023) & ~(uintptr_t)1023);
    float* e2raw = (float*)(SB + T_E2RAW);
    float* e2d   = (float*)(SB + T_E2D);
    float* z2p   = (float*)(SB + T_Z2P);
    float* z2raw = (float*)(SB + T_Z2RAW);
    float* z2pp  = (float*)(SB + T_Z2PP);
    float* rqm   = (float*)(SB + T_RQM);
    float* rqsum = (float*)(SB + T_RQS);
    float* qthr  = (float*)(SB + T_QTHR);
    float* rqs   = (float*)(SB + T_RQSI);
    u64*   keyA  = (u64*)(SB + T_KEY);
    int*   bmuS  = (int*)(SB + T_BMU);
    int*   cnt   = (int*)(SB + T_CNT);
    u32*   list  = (u32*)SB;               // overlays stage mem post-GEMM

    const int t = threadIdx.x, wid = t >> 5, lane = t & 31;
    const int g = lane >> 2, qd = lane & 3;
    const int R0 = blockIdx.x * TM;
    const int wr = (wid >> 2) * 32, wc = (wid & 3) * 64;

    // alpha (robust)
    int ai = Alpha[0];
    float aa = (ai > 0 && ai < 1000000) ? (float)ai : __int_as_float(ai);
    const float inva = 1.0f / aa;
    const float coef = -(aa + 1.0f) * 0.5f;
    const bool fast = (aa == 10.0f);
    const u64 cm2 = packf2(-2.f * inva, -2.f * inva);

    if (t < NNODES) {
        float e = g_e2[t];
        e2raw[t] = e;
        e2d[t]   = e * inva;
    }
    if (t == 0) *cnt = 0;
    if (t < TM) keyA[t] = ~0ull;

    // ---- GEMM: D = Z_tile(128x256) x E^T, bf16 HMMA, 4 k-chunks of 64 ----
    float acc[2][8][4];
    #pragma unroll
    for (int mt = 0; mt < 2; mt++)
        #pragma unroll
        for (int j = 0; j < 8; j++)
            #pragma unroll
            for (int c = 0; c < 4; c++) acc[mt][j][c] = 0.f;

    const int arow = t >> 2, akp = t & 3;   // A build: 4 threads/row, 16 floats each
    float z2acc = 0.f;

    // prologue: chunk 0 -> stage 0
    {
        const float4* zsrc = (const float4*)(Z + (size_t)(R0 + arow) * LATENT + akp * 16);
        float v[16];
        #pragma unroll
        for (int i = 0; i < 4; i++) *(float4*)(v + 4 * i) = zsrc[i];
        __nv_bfloat16 h[16];
        #pragma unroll
        for (int i = 0; i < 16; i++) { z2acc = fmaf(v[i], v[i], z2acc); h[i] = __float2bfloat16(v[i]); }
        *(uint4*)(SB + SA_OFF(0) + toff(arow, akp * 32))      = ((uint4*)h)[0];
        *(uint4*)(SB + SA_OFF(0) + toff(arow, akp * 32 + 16)) = ((uint4*)h)[1];
        #pragma unroll
        for (int i = 0; i < 4; i++) {
            int o = (t + NT * i) * 16;
            cp16(smaddr(SB + SB_OFF(0) + o), g_Bt[0] + o);
        }
        cp_commit();
    }

    for (int c = 0; c < 4; c++) {
        const int s = c & 1;
        cp_wait0();
        __syncthreads();           // stage s ready; stage s^1 consumers (chunk c-1) done

        if (c < 3) {               // issue chunk c+1 into stage s^1
            const float4* zsrc = (const float4*)(Z + (size_t)(R0 + arow) * LATENT + (c + 1) * 64 + akp * 16);
            float v[16];
            #pragma unroll
            for (int i = 0; i < 4; i++) *(float4*)(v + 4 * i) = zsrc[i];
            __nv_bfloat16 h[16];
            #pragma unroll
            for (int i = 0; i < 16; i++) { z2acc = fmaf(v[i], v[i], z2acc); h[i] = __float2bfloat16(v[i]); }
            *(uint4*)(SB + SA_OFF(1 - s) + toff(arow, akp * 32))      = ((uint4*)h)[0];
            *(uint4*)(SB + SA_OFF(1 - s) + toff(arow, akp * 32 + 16)) = ((uint4*)h)[1];
            #pragma unroll
            for (int i = 0; i < 4; i++) {
                int o = (t + NT * i) * 16;
                cp16(smaddr(SB + SB_OFF(1 - s) + o), g_Bt[c + 1] + o);
            }
            cp_commit();
        }

        // compute chunk c
        const u32 sAa = smaddr(SB + SA_OFF(s));
        const u32 sBa = smaddr(SB + SB_OFF(s));
        const int la = lane & 15, kh = lane >> 4;
        #pragma unroll
        for (int ks = 0; ks < 4; ks++) {
            const int kb = ks * 32 + kh * 16;
            u32 af[2][4];
            ldsm4(af[0], sAa + toff(wr + la, kb));
            ldsm4(af[1], sAa + toff(wr + 16 + la, kb));
            u32 bf[4][4];
            #pragma unroll
            for (int p = 0; p < 4; p++)
                ldsm4(bf[p], sBa + toff(wc + p * 16 + la, kb));
            #pragma unroll
            for (int mt = 0; mt < 2; mt++)
                #pragma unroll
                for (int j = 0; j < 8; j++)
                    mma16816(acc[mt][j], af[mt], bf[j >> 1][j & 1], bf[j >> 1][(j & 1) + 2]);
        }
    }

    // ---- z2 finalize ----
    z2p[arow * 4 + akp] = z2acc;
    __syncthreads();
    if (t < TM) {
        float z = z2p[4 * t] + z2p[4 * t + 1] + z2p[4 * t + 2] + z2p[4 * t + 3];
        z2raw[t] = z;
        z2pp[t]  = fmaf(z, inva, 1.0f);
    }
    __syncthreads();

    // ---- q eval (rsqrt(p^11) fast path), per-row qmax + qsum ----
    // thread rows: wr + mt*16 + g (c0,c1) and +8 (c2,c3); cols wc + j*8 + 2qd (+1)
    u64 ed2[8];
    #pragma unroll
    for (int j = 0; j < 8; j++) ed2[j] = *(const u64*)(e2d + wc + j * 8 + 2 * qd);

    float qmaxr[4], qsumr[4];
    #pragma unroll
    for (int mt = 0; mt < 2; mt++) {
        #pragma unroll
        for (int hf = 0; hf < 2; hf++) {
            const int row = wr + mt * 16 + hf * 8 + g;
            const u64 zp = packf2(z2pp[row], z2pp[row]);
            u64 qs2 = 0ull;
            float qmax = 0.f;
            #pragma unroll
            for (int j = 0; j < 8; j++) {
                u64 a2 = packf2(acc[mt][j][2 * hf], acc[mt][j][2 * hf + 1]);
                u64 p  = fma2(a2, cm2, add2(zp, ed2[j]));   // p = 1 + d*inva
                float q0, q1;
                if (fast) {
                    u64 x2 = mul2(p, p);
                    u64 x4 = mul2(x2, x2);
                    u64 x8 = mul2(x4, x4);
                    u64 x11 = mul2(mul2(x8, x2), p);
                    float lo, hi; unpackf2(lo, hi, x11);
                    q0 = rsqrtf(lo); q1 = rsqrtf(hi);
                } else {
                    float lo, hi; unpackf2(lo, hi, p);
                    q0 = exp2f(coef * __log2f(lo));
                    q1 = exp2f(coef * __log2f(hi));
                }
                qs2 = add2(qs2, packf2(q0, q1));
                qmax = fmaxf(qmax, fmaxf(q0, q1));
                acc[mt][j][2 * hf] = q0;                    // stash raw q
                acc[mt][j][2 * hf + 1] = q1;
            }
            float slo, shi; unpackf2(slo, shi, qs2);
            qmaxr[mt * 2 + hf] = qmax;
            qsumr[mt * 2 + hf] = slo + shi;
        }
    }
    // reduce over qd lanes (xor 1,2), then across 4 col-warps via smem
    #pragma unroll
    for (int i = 0; i < 4; i++) {
        qmaxr[i] = fmaxf(qmaxr[i], __shfl_xor_sync(0xffffffffu, qmaxr[i], 1));
        qmaxr[i] = fmaxf(qmaxr[i], __shfl_xor_sync(0xffffffffu, qmaxr[i], 2));
        qsumr[i] += __shfl_xor_sync(0xffffffffu, qsumr[i], 1);
        qsumr[i] += __shfl_xor_sync(0xffffffffu, qsumr[i], 2);
    }
    if (qd == 0) {
        #pragma unroll
        for (int i = 0; i < 4; i++) {
            const int row = wr + (i >> 1) * 16 + (i & 1) * 8 + g;
            rqm[row * 4 + (wid & 3)]   = qmaxr[i];
            rqsum[row * 4 + (wid & 3)] = qsumr[i];
        }
    }
    __syncthreads();
    if (t < TM) {
        float qm = 0.f, s = 0.f;
        #pragma unroll
        for (int k = 0; k < 4; k++) { qm = fmaxf(qm, rqm[t * 4 + k]); s += rqsum[t * 4 + k]; }
        rqs[t] = 1.0f / s;
        // q-threshold = q(d_min + MARGIN): invert qmax -> p_min, shift, re-evaluate
        float pmin = exp2f(__log2f(qm) / coef);
        float y = pmin + MARGIN * inva;
        float qt;
        if (fast) {
            float y2 = y * y, y4 = y2 * y2, y8 = y4 * y4;
            qt = rsqrtf(y8 * y2 * y);
        } else {
            qt = exp2f(coef * __log2f(y));
        }
        qthr[t] = qt;
    }
    __syncthreads();

    // ---- candidate collection (q >= qthr[row]) ----
    #pragma unroll
    for (int mt = 0; mt < 2; mt++)
        #pragma unroll
        for (int hf = 0; hf < 2; hf++) {
            const int row = wr + mt * 16 + hf * 8 + g;
            const float th = qthr[row];
            #pragma unroll
            for (int j = 0; j < 8; j++)
                #pragma unroll
                for (int u2 = 0; u2 < 2; u2++) {
                    if (acc[mt][j][2 * hf + u2] >= th) {
                        int idx = atomicAdd(cnt, 1);
                        if (idx < CAP)
                            list[idx] = ((u32)row << 8) | (u32)(wc + j * 8 + 2 * qd + u2);
                    }
                }
        }
    __syncthreads();

    // ---- exact fp32 refinement: one warp per candidate ----
    {
        const int n = min(*cnt, CAP);
        for (int e = wid; e < n; e += 16) {
            u32 ent = list[e];
            int row = ent >> 8, node = ent & 255;
            const float4* zr = (const float4*)(Z + (size_t)(R0 + row) * LATENT);
            const float4* er = (const float4*)(E + (size_t)node * LATENT);
            float4 za = zr[lane * 2], zb = zr[lane * 2 + 1];
            float4 ea = er[lane * 2], eb = er[lane * 2 + 1];
            float d = za.x*ea.x + za.y*ea.y + za.z*ea.z + za.w*ea.w
                    + zb.x*eb.x + zb.y*eb.y + zb.z*eb.z + zb.w*eb.w;
            #pragma unroll
            for (int o = 16; o > 0; o >>= 1) d += __shfl_down_sync(0xffffffffu, d, o);
            if (lane == 0) {
                float dex = fmaxf(z2raw[row] + e2raw[node] - 2.f * d, 0.f);
                u64 key = ((u64)__float_as_uint(dex) << 32) | (u64)node;
                atomicMin(&keyA[row], key);
            }
        }
    }
    __syncthreads();
    if (t < TM) bmuS[t] = (int)(keyA[t] & 0xffffffffu);
    __syncthreads();

    // ---- outputs: [z_q | z_q_neighbors | q | bmu] ----
    const size_t NBOFF  = (size_t)NROWS * 256;
    const size_t QOFF   = (size_t)NROWS * 1536;
    const size_t BMUOFF = (size_t)NROWS * 1792;

    // q normalized + eps, float2 stores
    #pragma unroll
    for (int mt = 0; mt < 2; mt++)
        #pragma unroll
        for (int hf = 0; hf < 2; hf++) {
            const int row = wr + mt * 16 + hf * 8 + g;
            const float rq = rqs[row];
            #pragma unroll
            for (int j = 0; j < 8; j++) {
                float2 qv;
                qv.x = fmaf(acc[mt][j][2 * hf],     rq, EPSF);
                qv.y = fmaf(acc[mt][j][2 * hf + 1], rq, EPSF);
                *(float2*)(out + QOFF + (size_t)(R0 + row) * NNODES + wc + j * 8 + 2 * qd) = qv;
            }
        }

    if (t < TM) out[BMUOFF + R0 + t] = (float)bmuS[t];

    // z_q + neighbor gathers: 6 copies/row, one warp per copy
    for (int cp = wid; cp < TM * 6; cp += 16) {
        int row2 = cp / 6;
        int s    = cp - row2 * 6;
        int b    = bmuS[row2];
        int idx;
        if (s <= 1) {
            idx = b;
        } else {
            int k1 = b >> 4, k2 = b & 15;
            if      (s == 2) idx = (((k1 + 15) & 15) << 4) + k2;   // up
            else if (s == 3) idx = (((k1 + 1)  & 15) << 4) + k2;   // down
            else if (s == 4) idx = (k1 << 4) + ((k2 + 1)  & 15);   // right
            else             idx = (k1 << 4) + ((k2 + 15) & 15);   // left
        }
        const float4* src = (const float4*)(E + (size_t)idx * LATENT);
        float4 a0 = src[lane], a1 = src[lane + 32];
        float* dstp = (s == 0)
            ? out + (size_t)(R0 + row2) * LATENT
            : out + NBOFF + ((size_t)(R0 + row2) * 5 + (s - 1)) * LATENT;
        float4* d4 = (float4*)dstp;
        d4[lane]      = a0;
        d4[lane + 32] = a1;
    }
}

extern "C" void kernel_launch(void* const* d_in, const int* in_sizes, int n_in,
                              void* d_out, int out_size) {
    const float* Z = (const float*)d_in[0];
    const float* E = (const float*)d_in[1];
    const int*   A = (const int*)d_in[2];
    float* out = (float*)d_out;

    prep_kernel<<<8, 256>>>(E);
    cudaFuncSetAttribute(som_main, cudaFuncAttributeMaxDynamicSharedMemorySize, SMEM_BYTES);
    som_main<<<NROWS / TM, NT, SMEM_BYTES>>>(Z, E, A, out);
}